// round 3
// baseline (speedup 1.0000x reference)
#include <cuda_runtime.h>
#include <stdint.h>

#define BB   8
#define NN   8192
#define CIN  64
#define COUT 128
#define MM   2048
#define KNN  16
#define ROWS (BB*NN)            // 65536
#define Y_SIZE ((size_t)BB*MM*COUT)

// ---------------- scratch (static device globals; no allocations) ----------------
__device__ float g_h[(size_t)ROWS*COUT];     // raw h = x @ W^T  (32 MB)
__device__ int   g_nbr[(size_t)BB*MM*KNN];   // kNN indices
__device__ float g_psum[256*COUT];
__device__ float g_psq [256*COUT];
__device__ float g_scale[COUT];
__device__ float g_shift[COUT];

// =============================== FPS ===============================
// One block per batch. Each thread owns 8 contiguous points + mindist in
// registers. smem holds a read-only copy of positions for the winner
// broadcast. Distance math uses non-contracted rn ops (matches XLA's fused
// elementwise+reduce code — verified bit-exact: no trajectory divergence).
#define FPS_PT 8
__global__ void __launch_bounds__(1024, 1)
fps_kernel(const float* __restrict__ p1, float* __restrict__ p2out) {
    extern __shared__ float sm[];
    float* px = sm; float* py = sm + NN; float* pz = sm + 2*NN;
    __shared__ unsigned long long wred[32];
    __shared__ unsigned long long s_key;
    const int b = blockIdx.x;
    const int tid = threadIdx.x;
    const float* p = p1 + (size_t)b*NN*3;

    float X[FPS_PT], Y[FPS_PT], Z[FPS_PT], MD[FPS_PT];
    {
        const float4* pv = (const float4*)(p + (size_t)tid*FPS_PT*3);
        float buf[24];
        #pragma unroll
        for (int i = 0; i < 6; i++) {
            float4 v = pv[i];
            buf[i*4+0]=v.x; buf[i*4+1]=v.y; buf[i*4+2]=v.z; buf[i*4+3]=v.w;
        }
        #pragma unroll
        for (int k = 0; k < FPS_PT; k++) {
            X[k]=buf[k*3]; Y[k]=buf[k*3+1]; Z[k]=buf[k*3+2]; MD[k]=1e10f;
            px[tid*FPS_PT+k]=X[k]; py[tid*FPS_PT+k]=Y[k]; pz[tid*FPS_PT+k]=Z[k];
        }
    }
    if (tid == 0) {
        size_t o0 = (size_t)b*MM*3;
        p2out[o0+0]=p[0]; p2out[o0+1]=p[1]; p2out[o0+2]=p[2];
    }
    __syncthreads();
    float lx = px[0], ly = py[0], lz = pz[0];

    for (int j = 1; j < MM; j++) {
        float bv = -1.0f; int bi = 0;
        #pragma unroll
        for (int k = 0; k < FPS_PT; k++) {
            float dx = __fsub_rn(X[k], lx);
            float dy = __fsub_rn(Y[k], ly);
            float dz = __fsub_rn(Z[k], lz);
            float d  = __fadd_rn(__fadd_rn(__fmul_rn(dx,dx), __fmul_rn(dy,dy)), __fmul_rn(dz,dz));
            float m  = fminf(MD[k], d);
            MD[k] = m;
            if (m > bv) { bv = m; bi = tid*FPS_PT + k; }   // first-max within thread
        }
        // pack (value, inverted idx): max key -> max value, tie -> lowest idx
        unsigned long long key =
            ((unsigned long long)__float_as_uint(bv) << 32) | (unsigned)(NN-1-bi);
        #pragma unroll
        for (int o = 16; o; o >>= 1) {
            unsigned long long t = __shfl_xor_sync(0xffffffffu, key, o);
            if (t > key) key = t;
        }
        if ((tid & 31) == 0) wred[tid >> 5] = key;
        __syncthreads();
        if (tid < 32) {
            key = wred[tid];
            #pragma unroll
            for (int o = 16; o; o >>= 1) {
                unsigned long long t = __shfl_xor_sync(0xffffffffu, key, o);
                if (t > key) key = t;
            }
            if (tid == 0) {
                s_key = key;
                int idx = (NN-1) - (int)(key & 0xffffffffu);
                size_t o2 = (size_t)(b*MM + j)*3;
                p2out[o2]=px[idx]; p2out[o2+1]=py[idx]; p2out[o2+2]=pz[idx];
            }
        }
        __syncthreads();
        int idx = (NN-1) - (int)(s_key & 0xffffffffu);
        lx = px[idx]; ly = py[idx]; lz = pz[idx];
    }
}

// =============================== GEMM ===============================
// h[r][o] = sum_c x[r][c]*W[o][c], exact fp32, k-ascending FFMA chain from a
// zero accumulator — bit-matches cuBLAS SGEMM's inner loop.
__global__ void __launch_bounds__(256)
gemm_kernel(const float* __restrict__ x, const float* __restrict__ W) {
    extern __shared__ float sm[];
    float* xs = sm;                // [128][65] padded
    float* ws = sm + 128*65;       // [64][128] = W^T
    const int tid = threadIdx.x;
    const size_t rb = (size_t)blockIdx.x * 128;
    const float* gx = x + rb*CIN;

    for (int i = tid; i < 128*CIN; i += 256) {
        int r = i >> 6, c = i & 63;
        xs[r*65 + c] = gx[i];
    }
    for (int i = tid; i < COUT*CIN; i += 256) {
        int o = i >> 6, c = i & 63;
        ws[c*COUT + o] = W[i];
    }
    __syncthreads();

    const int tx = tid & 15, ty = tid >> 4;
    const int r0 = ty*8, o0 = tx*8;
    float acc[8][8];
    #pragma unroll
    for (int i = 0; i < 8; i++)
        #pragma unroll
        for (int j = 0; j < 8; j++) acc[i][j] = 0.f;

    for (int c = 0; c < CIN; c++) {
        float a[8];
        #pragma unroll
        for (int i = 0; i < 8; i++) a[i] = xs[(r0+i)*65 + c];
        float4 b0 = *(const float4*)&ws[c*COUT + o0];
        float4 b1 = *(const float4*)&ws[c*COUT + o0 + 4];
        float bb[8] = {b0.x,b0.y,b0.z,b0.w,b1.x,b1.y,b1.z,b1.w};
        #pragma unroll
        for (int i = 0; i < 8; i++)
            #pragma unroll
            for (int j = 0; j < 8; j++) acc[i][j] = __fmaf_rn(a[i], bb[j], acc[i][j]);
    }
    #pragma unroll
    for (int i = 0; i < 8; i++) {
        float* out = &g_h[(rb + r0 + i)*COUT + o0];
        *(float4*)out       = make_float4(acc[i][0],acc[i][1],acc[i][2],acc[i][3]);
        *(float4*)(out + 4) = make_float4(acc[i][4],acc[i][5],acc[i][6],acc[i][7]);
    }
}

// ====================== BN stats (deterministic 2-stage) ======================
__global__ void __launch_bounds__(128) bnstat1() {
    const int c = threadIdx.x;
    const int blk = blockIdx.x;                  // 256 blocks x 256 rows
    const float* base = g_h + (size_t)blk*256*COUT;
    float s = 0.f, q = 0.f;
    for (int r = 0; r < 256; r++) {
        float v = base[(size_t)r*COUT + c];
        s += v; q = __fmaf_rn(v, v, q);
    }
    g_psum[blk*COUT + c] = s;
    g_psq [blk*COUT + c] = q;
}

__global__ void __launch_bounds__(128)
bnstat2(const float* __restrict__ gamma, const float* __restrict__ beta) {
    const int c = threadIdx.x;
    double s = 0.0, q = 0.0;
    for (int b = 0; b < 256; b++) { s += g_psum[b*COUT+c]; q += g_psq[b*COUT+c]; }
    double mean = s / (double)ROWS;
    double var  = q / (double)ROWS - mean*mean;
    double inv  = 1.0 / sqrt(var + 1e-5);
    float sc = (float)inv * gamma[c];
    g_scale[c] = sc;
    g_shift[c] = __fmaf_rn(-(float)mean, sc, beta[c]);
}

// =============================== kNN ===============================
// One warp per query. Per-lane register top-16 (packed sortable keys),
// warp merge by 16x min-extraction.
// d2 = (s2 - 2*dot) + s1 with:
//   s1, s2 : separate rn mul/add  (XLA fused elementwise+reduce — no FMA)
//   dot    : FFMA chain, k-ascending from rn(x*qx)  (cuBLAS SGEMM inner loop)
__device__ __forceinline__ unsigned f2key(float d) {
    unsigned u = __float_as_uint(d);
    return u ^ ((u >> 31) ? 0xFFFFFFFFu : 0x80000000u);
}

__global__ void __launch_bounds__(256)
knn_kernel(const float* __restrict__ p1, const float* __restrict__ p2) {
    extern __shared__ float sm[];
    float* px = sm; float* py = sm+NN; float* pz = sm+2*NN; float* s1 = sm+3*NN;
    const int tid = threadIdx.x;
    const int b  = blockIdx.x >> 8;       // 256 blocks per batch
    const int mg = blockIdx.x & 255;
    const float* p = p1 + (size_t)b*NN*3;

    for (int i = tid; i < NN*3; i += 256) {
        float v = p[i];
        int pt = i / 3, d = i - pt*3;
        (d == 0 ? px : (d == 1 ? py : pz))[pt] = v;
    }
    __syncthreads();
    for (int i = tid; i < NN; i += 256)
        s1[i] = __fadd_rn(__fadd_rn(__fmul_rn(px[i],px[i]), __fmul_rn(py[i],py[i])), __fmul_rn(pz[i],pz[i]));
    __syncthreads();

    const int w = tid >> 5, lane = tid & 31;
    const int m = mg*8 + w;
    const size_t qi = (size_t)b*MM + m;
    const float qx = p2[qi*3], qy = p2[qi*3+1], qz = p2[qi*3+2];
    const float s2 = __fadd_rn(__fadd_rn(__fmul_rn(qx,qx), __fmul_rn(qy,qy)), __fmul_rn(qz,qz));

    // init keys = key(3.4e38) | idx 0xffffffff (so threshold recovery stays finite)
    const unsigned long long INITK =
        ((unsigned long long)0xFF7FFFFFu << 32) | 0xFFFFFFFFu;
    unsigned long long bk[KNN];
    #pragma unroll
    for (int k = 0; k < KNN; k++) bk[k] = INITK;
    float thr = 3.4e38f;

    for (int i = lane; i < NN; i += 32) {
        // cuBLAS-style FFMA chain for the einsum dot product
        float dot = __fmaf_rn(pz[i], qz, __fmaf_rn(py[i], qy, __fmul_rn(px[i], qx)));
        float d   = __fadd_rn(__fsub_rn(s2, __fmul_rn(2.0f, dot)), s1[i]);
        if (d < thr) {   // equal -> keep earlier index (top_k stability)
            unsigned long long nk = ((unsigned long long)f2key(d) << 32) | (unsigned)i;
            unsigned long long mk = 0; int mp = 0;
            #pragma unroll
            for (int k = 0; k < KNN; k++) if (bk[k] > mk) { mk = bk[k]; mp = k; }
            #pragma unroll
            for (int k = 0; k < KNN; k++) if (k == mp) bk[k] = nk;
            mk = 0;
            #pragma unroll
            for (int k = 0; k < KNN; k++) if (bk[k] > mk) mk = bk[k];
            unsigned hv = (unsigned)(mk >> 32);
            hv = (hv & 0x80000000u) ? (hv ^ 0x80000000u) : ~hv;
            thr = __uint_as_float(hv);
        }
    }

    // warp merge: extract global 16 smallest (keys unique: idx distinct per lane)
    unsigned long long res = 0;
    for (int r = 0; r < KNN; r++) {
        unsigned long long lm = 0xFFFFFFFFFFFFFFFFull;
        #pragma unroll
        for (int k = 0; k < KNN; k++) if (bk[k] < lm) lm = bk[k];
        unsigned long long wm = lm;
        #pragma unroll
        for (int o = 16; o; o >>= 1) {
            unsigned long long t = __shfl_xor_sync(0xffffffffu, wm, o);
            if (t < wm) wm = t;
        }
        if (lm == wm) {
            #pragma unroll
            for (int k = 0; k < KNN; k++) if (bk[k] == wm) bk[k] = 0xFFFFFFFFFFFFFFFFull;
        }
        if (lane == r) res = wm;
    }
    if (lane < KNN) g_nbr[qi*KNN + lane] = (int)(res & 0xFFFFFFFFu);
}

// =========================== gather + BN + ReLU + max ===========================
__global__ void __launch_bounds__(256)
gather_kernel(float* __restrict__ y) {
    const int tid = threadIdx.x;
    const int w = tid >> 5, lane = tid & 31;
    const int q = blockIdx.x*8 + w;              // global (b,m) id
    const int b = q >> 11;
    const int* nb = g_nbr + (size_t)q*KNN;
    const float4 sc = *(const float4*)&g_scale[lane*4];
    const float4 sh = *(const float4*)&g_shift[lane*4];
    const float* hb = g_h + (size_t)b*NN*COUT;

    float4 acc = make_float4(-3.4e38f,-3.4e38f,-3.4e38f,-3.4e38f);
    #pragma unroll
    for (int k = 0; k < KNN; k++) {
        int n = nb[k];
        float4 v = *(const float4*)&hb[(size_t)n*COUT + lane*4];
        float f;
        f = fmaxf(__fmaf_rn(v.x, sc.x, sh.x), 0.f); acc.x = fmaxf(acc.x, f);
        f = fmaxf(__fmaf_rn(v.y, sc.y, sh.y), 0.f); acc.y = fmaxf(acc.y, f);
        f = fmaxf(__fmaf_rn(v.z, sc.z, sh.z), 0.f); acc.z = fmaxf(acc.z, f);
        f = fmaxf(__fmaf_rn(v.w, sc.w, sh.w), 0.f); acc.w = fmaxf(acc.w, f);
    }
    *(float4*)&y[(size_t)q*COUT + lane*4] = acc;
}

// =============================== launch ===============================
extern "C" void kernel_launch(void* const* d_in, const int* in_sizes, int n_in,
                              void* d_out, int out_size) {
    const float* x     = (const float*)d_in[0];
    const float* p1    = (const float*)d_in[1];
    const float* W     = (const float*)d_in[2];
    const float* gamma = (const float*)d_in[3];
    const float* beta  = (const float*)d_in[4];
    float* y  = (float*)d_out;
    float* p2 = y + Y_SIZE;

    const int FPS_SMEM  = 3*NN*4;          // 96 KB
    const int KNN_SMEM  = 4*NN*4;          // 128 KB
    const int GEMM_SMEM = (128*65 + 64*128)*4;

    cudaFuncSetAttribute(fps_kernel,  cudaFuncAttributeMaxDynamicSharedMemorySize, FPS_SMEM);
    cudaFuncSetAttribute(knn_kernel,  cudaFuncAttributeMaxDynamicSharedMemorySize, KNN_SMEM);
    cudaFuncSetAttribute(gemm_kernel, cudaFuncAttributeMaxDynamicSharedMemorySize, GEMM_SMEM);

    fps_kernel<<<BB, 1024, FPS_SMEM>>>(p1, p2);
    gemm_kernel<<<ROWS/128, 256, GEMM_SMEM>>>(x, W);
    bnstat1<<<256, 128>>>();
    bnstat2<<<1, 128>>>(gamma, beta);
    knn_kernel<<<BB*(MM/8), 256, KNN_SMEM>>>(p1, p2);
    gather_kernel<<<(BB*MM)/8, 256>>>(y);
}

// round 4
// speedup vs baseline: 1.0418x; 1.0418x over previous
#include <cuda_runtime.h>
#include <stdint.h>

#define BB   8
#define NN   8192
#define CIN  64
#define COUT 128
#define MM   2048
#define KNN  16
#define ROWS (BB*NN)            // 65536
#define Y_SIZE ((size_t)BB*MM*COUT)

// ---------------- scratch (static device globals; no allocations) ----------------
__device__ float g_h[(size_t)ROWS*COUT];     // raw h = x @ W^T  (32 MB)
__device__ int   g_nbr[(size_t)BB*MM*KNN];   // kNN indices
__device__ float g_psum[256*COUT];
__device__ float g_psq [256*COUT];
__device__ float g_scale[COUT];
__device__ float g_shift[COUT];

// -------- packed f32x2 helpers (sm_100+; per-lane bits == scalar rn ops) --------
#define ADD_F32X2(out, a, b) \
    asm("add.rn.f32x2 %0, %1, %2;" : "=l"(out) : "l"(a), "l"(b))
#define MUL_F32X2(out, a, b) \
    asm("mul.rn.f32x2 %0, %1, %2;" : "=l"(out) : "l"(a), "l"(b))
#define PACK_F32X2(out, lo, hi) \
    asm("mov.b64 %0, {%1, %2};" : "=l"(out) : "f"(lo), "f"(hi))
#define UNPACK_F32X2(lo, hi, in) \
    asm("mov.b64 {%0, %1}, %2;" : "=f"(lo), "=f"(hi) : "l"(in))

// =============================== FPS ===============================
// One block per batch, 1024 threads, 8 points/thread in registers.
// Distance math: packed f32x2 with the exact scalar rounding pattern
// dx=X-lx (as X+(-lx)), d=(dx^2+dy^2)+dz^2 — bit-identical to XLA's fused
// elementwise+reduce (verified: trajectory bit-exact since R3).
// Reduction: warp shfl-max on packed (value,inv-idx) keys, then 32 leaders
// atomicMax into a 3-slot smem ring (reset 2 iterations ahead of reuse —
// separated from readers/writers by barriers), ONE __syncthreads per iter.
__global__ void __launch_bounds__(1024, 1)
fps_kernel(const float* __restrict__ p1, float* __restrict__ p2out) {
    extern __shared__ float sm[];
    float* px = sm; float* py = sm + NN; float* pz = sm + 2*NN;
    __shared__ unsigned long long slots[3];
    const int b = blockIdx.x;
    const int tid = threadIdx.x;
    const float* p = p1 + (size_t)b*NN*3;

    float X[8], Y[8], Z[8], MD[8];
    unsigned long long Xp[4], Yp[4], Zp[4];
    {
        const float4* pv = (const float4*)(p + (size_t)tid*8*3);
        float buf[24];
        #pragma unroll
        for (int i = 0; i < 6; i++) {
            float4 v = pv[i];
            buf[i*4+0]=v.x; buf[i*4+1]=v.y; buf[i*4+2]=v.z; buf[i*4+3]=v.w;
        }
        #pragma unroll
        for (int k = 0; k < 8; k++) {
            X[k]=buf[k*3]; Y[k]=buf[k*3+1]; Z[k]=buf[k*3+2]; MD[k]=1e10f;
            px[tid*8+k]=X[k]; py[tid*8+k]=Y[k]; pz[tid*8+k]=Z[k];
        }
        #pragma unroll
        for (int i = 0; i < 4; i++) {
            PACK_F32X2(Xp[i], X[2*i], X[2*i+1]);
            PACK_F32X2(Yp[i], Y[2*i], Y[2*i+1]);
            PACK_F32X2(Zp[i], Z[2*i], Z[2*i+1]);
        }
    }
    if (tid < 3) slots[tid] = 0ull;
    if (tid == 0) {
        size_t o0 = (size_t)b*MM*3;
        p2out[o0+0]=p[0]; p2out[o0+1]=p[1]; p2out[o0+2]=p[2];
    }
    __syncthreads();
    float lx = px[0], ly = py[0], lz = pz[0];

    for (int j = 1; j < MM; j++) {
        float nlx = -lx, nly = -ly, nlz = -lz;
        unsigned long long nlx2, nly2, nlz2;
        PACK_F32X2(nlx2, nlx, nlx);
        PACK_F32X2(nly2, nly, nly);
        PACK_F32X2(nlz2, nlz, nlz);

        #pragma unroll
        for (int i = 0; i < 4; i++) {
            unsigned long long dx, dy, dz, sx, sy, sz, s, d;
            ADD_F32X2(dx, Xp[i], nlx2);          // X + (-lx)  == X - lx (bitwise)
            ADD_F32X2(dy, Yp[i], nly2);
            ADD_F32X2(dz, Zp[i], nlz2);
            MUL_F32X2(sx, dx, dx);
            MUL_F32X2(sy, dy, dy);
            MUL_F32X2(sz, dz, dz);
            ADD_F32X2(s,  sx, sy);               // (dx^2+dy^2)
            ADD_F32X2(d,  s,  sz);               // ... + dz^2
            float d0, d1; UNPACK_F32X2(d0, d1, d);
            MD[2*i]   = fminf(MD[2*i],   d0);
            MD[2*i+1] = fminf(MD[2*i+1], d1);
        }

        // thread-local argmax: max tree, then lowest matching k
        float bv = MD[0];
        #pragma unroll
        for (int k = 1; k < 8; k++) bv = fmaxf(bv, MD[k]);
        int bi = 7;
        #pragma unroll
        for (int k = 6; k >= 0; k--) if (MD[k] == bv) bi = k;

        // packed key: max value wins, tie -> lowest global index
        unsigned long long key =
            ((unsigned long long)__float_as_uint(bv) << 32) | (unsigned)(NN-1-(tid*8+bi));
        #pragma unroll
        for (int o = 16; o; o >>= 1) {
            unsigned long long t = __shfl_xor_sync(0xffffffffu, key, o);
            if (t > key) key = t;
        }
        if ((tid & 31) == 0) atomicMax(&slots[j % 3], key);
        if (tid == 33) slots[(j + 1) % 3] = 0ull;   // reset 2 iters before reuse
        __syncthreads();

        unsigned long long wkey = slots[j % 3];
        int idx = (NN-1) - (int)(wkey & 0xffffffffu);
        if (tid == 0) {
            size_t o2 = (size_t)(b*MM + j)*3;
            p2out[o2]=px[idx]; p2out[o2+1]=py[idx]; p2out[o2+2]=pz[idx];
        }
        lx = px[idx]; ly = py[idx]; lz = pz[idx];
    }
}

// =============================== GEMM ===============================
// h[r][o] = sum_c x[r][c]*W[o][c], exact fp32, k-ascending FFMA chain from a
// zero accumulator — bit-matches cuBLAS SGEMM's inner loop.
__global__ void __launch_bounds__(256)
gemm_kernel(const float* __restrict__ x, const float* __restrict__ W) {
    extern __shared__ float sm[];
    float* xs = sm;                // [128][65] padded
    float* ws = sm + 128*65;       // [64][128] = W^T
    const int tid = threadIdx.x;
    const size_t rb = (size_t)blockIdx.x * 128;
    const float* gx = x + rb*CIN;

    for (int i = tid; i < 128*CIN; i += 256) {
        int r = i >> 6, c = i & 63;
        xs[r*65 + c] = gx[i];
    }
    for (int i = tid; i < COUT*CIN; i += 256) {
        int o = i >> 6, c = i & 63;
        ws[c*COUT + o] = W[i];
    }
    __syncthreads();

    const int tx = tid & 15, ty = tid >> 4;
    const int r0 = ty*8, o0 = tx*8;
    float acc[8][8];
    #pragma unroll
    for (int i = 0; i < 8; i++)
        #pragma unroll
        for (int j = 0; j < 8; j++) acc[i][j] = 0.f;

    for (int c = 0; c < CIN; c++) {
        float a[8];
        #pragma unroll
        for (int i = 0; i < 8; i++) a[i] = xs[(r0+i)*65 + c];
        float4 b0 = *(const float4*)&ws[c*COUT + o0];
        float4 b1 = *(const float4*)&ws[c*COUT + o0 + 4];
        float bb[8] = {b0.x,b0.y,b0.z,b0.w,b1.x,b1.y,b1.z,b1.w};
        #pragma unroll
        for (int i = 0; i < 8; i++)
            #pragma unroll
            for (int j = 0; j < 8; j++) acc[i][j] = __fmaf_rn(a[i], bb[j], acc[i][j]);
    }
    #pragma unroll
    for (int i = 0; i < 8; i++) {
        float* out = &g_h[(rb + r0 + i)*COUT + o0];
        *(float4*)out       = make_float4(acc[i][0],acc[i][1],acc[i][2],acc[i][3]);
        *(float4*)(out + 4) = make_float4(acc[i][4],acc[i][5],acc[i][6],acc[i][7]);
    }
}

// ====================== BN stats (deterministic 2-stage) ======================
__global__ void __launch_bounds__(128) bnstat1() {
    const int c = threadIdx.x;
    const int blk = blockIdx.x;                  // 256 blocks x 256 rows
    const float* base = g_h + (size_t)blk*256*COUT;
    float s = 0.f, q = 0.f;
    for (int r = 0; r < 256; r++) {
        float v = base[(size_t)r*COUT + c];
        s += v; q = __fmaf_rn(v, v, q);
    }
    g_psum[blk*COUT + c] = s;
    g_psq [blk*COUT + c] = q;
}

__global__ void __launch_bounds__(1024)
bnstat2(const float* __restrict__ gamma, const float* __restrict__ beta) {
    const int t = threadIdx.x;
    const int c = t >> 3, part = t & 7;
    double s = 0.0, q = 0.0;
    for (int b = part; b < 256; b += 8) { s += g_psum[b*COUT+c]; q += g_psq[b*COUT+c]; }
    #pragma unroll
    for (int o = 4; o; o >>= 1) {
        s += __shfl_down_sync(0xffffffffu, s, o, 8);
        q += __shfl_down_sync(0xffffffffu, q, o, 8);
    }
    if (part == 0) {
        double mean = s / (double)ROWS;
        double var  = q / (double)ROWS - mean*mean;
        double inv  = 1.0 / sqrt(var + 1e-5);
        float sc = (float)inv * gamma[c];
        g_scale[c] = sc;
        g_shift[c] = __fmaf_rn(-(float)mean, sc, beta[c]);
    }
}

// =============================== kNN ===============================
// One warp per query. Per-lane register top-16 (packed sortable keys),
// warp merge by 16x min-extraction.
// d2 = (s2 - 2*dot) + s1 with:
//   s1, s2 : separate rn mul/add  (XLA fused elementwise+reduce — no FMA)
//   dot    : FFMA chain, k-ascending from rn(x*qx)  (cuBLAS SGEMM inner loop)
__device__ __forceinline__ unsigned f2key(float d) {
    unsigned u = __float_as_uint(d);
    return u ^ ((u >> 31) ? 0xFFFFFFFFu : 0x80000000u);
}

__global__ void __launch_bounds__(256)
knn_kernel(const float* __restrict__ p1, const float* __restrict__ p2) {
    extern __shared__ float sm[];
    float* px = sm; float* py = sm+NN; float* pz = sm+2*NN; float* s1 = sm+3*NN;
    const int tid = threadIdx.x;
    const int b  = blockIdx.x >> 8;       // 256 blocks per batch
    const int mg = blockIdx.x & 255;
    const float* p = p1 + (size_t)b*NN*3;

    for (int i = tid; i < NN*3; i += 256) {
        float v = p[i];
        int pt = i / 3, d = i - pt*3;
        (d == 0 ? px : (d == 1 ? py : pz))[pt] = v;
    }
    __syncthreads();
    for (int i = tid; i < NN; i += 256)
        s1[i] = __fadd_rn(__fadd_rn(__fmul_rn(px[i],px[i]), __fmul_rn(py[i],py[i])), __fmul_rn(pz[i],pz[i]));
    __syncthreads();

    const int w = tid >> 5, lane = tid & 31;
    const int m = mg*8 + w;
    const size_t qi = (size_t)b*MM + m;
    const float qx = p2[qi*3], qy = p2[qi*3+1], qz = p2[qi*3+2];
    const float s2 = __fadd_rn(__fadd_rn(__fmul_rn(qx,qx), __fmul_rn(qy,qy)), __fmul_rn(qz,qz));

    const unsigned long long INITK =
        ((unsigned long long)0xFF7FFFFFu << 32) | 0xFFFFFFFFu;
    unsigned long long bk[KNN];
    #pragma unroll
    for (int k = 0; k < KNN; k++) bk[k] = INITK;
    float thr = 3.4e38f;

    for (int i = lane; i < NN; i += 32) {
        float dot = __fmaf_rn(pz[i], qz, __fmaf_rn(py[i], qy, __fmul_rn(px[i], qx)));
        float d   = __fadd_rn(__fsub_rn(s2, __fmul_rn(2.0f, dot)), s1[i]);
        if (d < thr) {   // equal -> keep earlier index (top_k stability)
            unsigned long long nk = ((unsigned long long)f2key(d) << 32) | (unsigned)i;
            unsigned long long mk = 0; int mp = 0;
            #pragma unroll
            for (int k = 0; k < KNN; k++) if (bk[k] > mk) { mk = bk[k]; mp = k; }
            #pragma unroll
            for (int k = 0; k < KNN; k++) if (k == mp) bk[k] = nk;
            mk = 0;
            #pragma unroll
            for (int k = 0; k < KNN; k++) if (bk[k] > mk) mk = bk[k];
            unsigned hv = (unsigned)(mk >> 32);
            hv = (hv & 0x80000000u) ? (hv ^ 0x80000000u) : ~hv;
            thr = __uint_as_float(hv);
        }
    }

    unsigned long long res = 0;
    for (int r = 0; r < KNN; r++) {
        unsigned long long lm = 0xFFFFFFFFFFFFFFFFull;
        #pragma unroll
        for (int k = 0; k < KNN; k++) if (bk[k] < lm) lm = bk[k];
        unsigned long long wm = lm;
        #pragma unroll
        for (int o = 16; o; o >>= 1) {
            unsigned long long t = __shfl_xor_sync(0xffffffffu, wm, o);
            if (t < wm) wm = t;
        }
        if (lm == wm) {
            #pragma unroll
            for (int k = 0; k < KNN; k++) if (bk[k] == wm) bk[k] = 0xFFFFFFFFFFFFFFFFull;
        }
        if (lane == r) res = wm;
    }
    if (lane < KNN) g_nbr[qi*KNN + lane] = (int)(res & 0xFFFFFFFFu);
}

// =========================== gather + BN + ReLU + max ===========================
__global__ void __launch_bounds__(256)
gather_kernel(float* __restrict__ y) {
    const int tid = threadIdx.x;
    const int w = tid >> 5, lane = tid & 31;
    const int q = blockIdx.x*8 + w;              // global (b,m) id
    const int b = q >> 11;
    const int* nb = g_nbr + (size_t)q*KNN;
    const float4 sc = *(const float4*)&g_scale[lane*4];
    const float4 sh = *(const float4*)&g_shift[lane*4];
    const float* hb = g_h + (size_t)b*NN*COUT;

    float4 acc = make_float4(-3.4e38f,-3.4e38f,-3.4e38f,-3.4e38f);
    #pragma unroll
    for (int k = 0; k < KNN; k++) {
        int n = nb[k];
        float4 v = *(const float4*)&hb[(size_t)n*COUT + lane*4];
        float f;
        f = fmaxf(__fmaf_rn(v.x, sc.x, sh.x), 0.f); acc.x = fmaxf(acc.x, f);
        f = fmaxf(__fmaf_rn(v.y, sc.y, sh.y), 0.f); acc.y = fmaxf(acc.y, f);
        f = fmaxf(__fmaf_rn(v.z, sc.z, sh.z), 0.f); acc.z = fmaxf(acc.z, f);
        f = fmaxf(__fmaf_rn(v.w, sc.w, sh.w), 0.f); acc.w = fmaxf(acc.w, f);
    }
    *(float4*)&y[(size_t)q*COUT + lane*4] = acc;
}

// =============================== launch ===============================
extern "C" void kernel_launch(void* const* d_in, const int* in_sizes, int n_in,
                              void* d_out, int out_size) {
    const float* x     = (const float*)d_in[0];
    const float* p1    = (const float*)d_in[1];
    const float* W     = (const float*)d_in[2];
    const float* gamma = (const float*)d_in[3];
    const float* beta  = (const float*)d_in[4];
    float* y  = (float*)d_out;
    float* p2 = y + Y_SIZE;

    const int FPS_SMEM  = 3*NN*4;          // 96 KB
    const int KNN_SMEM  = 4*NN*4;          // 128 KB
    const int GEMM_SMEM = (128*65 + 64*128)*4;

    cudaFuncSetAttribute(fps_kernel,  cudaFuncAttributeMaxDynamicSharedMemorySize, FPS_SMEM);
    cudaFuncSetAttribute(knn_kernel,  cudaFuncAttributeMaxDynamicSharedMemorySize, KNN_SMEM);
    cudaFuncSetAttribute(gemm_kernel, cudaFuncAttributeMaxDynamicSharedMemorySize, GEMM_SMEM);

    fps_kernel<<<BB, 1024, FPS_SMEM>>>(p1, p2);
    gemm_kernel<<<ROWS/128, 256, GEMM_SMEM>>>(x, W);
    bnstat1<<<256, 128>>>();
    bnstat2<<<1, 1024>>>(gamma, beta);
    knn_kernel<<<BB*(MM/8), 256, KNN_SMEM>>>(p1, p2);
    gather_kernel<<<(BB*MM)/8, 256>>>(y);
}

// round 5
// speedup vs baseline: 1.1464x; 1.1005x over previous
#include <cuda_runtime.h>
#include <stdint.h>

#define BB   8
#define NN   8192
#define CIN  64
#define COUT 128
#define MM   2048
#define KNN  16
#define ROWS (BB*NN)            // 65536
#define Y_SIZE ((size_t)BB*MM*COUT)

// ---------------- scratch (static device globals; no allocations) ----------------
__device__ float g_h[(size_t)ROWS*COUT];     // raw h = x @ W^T  (32 MB)
__device__ int   g_nbr[(size_t)BB*MM*KNN];   // kNN indices
__device__ float g_psum[256*COUT];
__device__ float g_psq [256*COUT];
__device__ float g_scale[COUT];
__device__ float g_shift[COUT];

// -------- packed f32x2 helpers (sm_100+; per-lane bits == scalar rn ops) --------
#define ADD_F32X2(out, a, b) \
    asm("add.rn.f32x2 %0, %1, %2;" : "=l"(out) : "l"(a), "l"(b))
#define MUL_F32X2(out, a, b) \
    asm("mul.rn.f32x2 %0, %1, %2;" : "=l"(out) : "l"(a), "l"(b))
#define PACK_F32X2(out, lo, hi) \
    asm("mov.b64 %0, {%1, %2};" : "=l"(out) : "f"(lo), "f"(hi))
#define UNPACK_F32X2(lo, hi, in) \
    asm("mov.b64 {%0, %1}, %2;" : "=f"(lo), "=f"(hi) : "l"(in))

// =============================== FPS ===============================
// One block per batch, 512 threads, 16 points/thread in registers.
// Distance math: packed f32x2 with the exact scalar rounding pattern
// dx=X+(-lx), d=(dx^2+dy^2)+dz^2 — bit-identical to XLA (trajectory verified).
// Reduction per iteration: warp butterfly on packed (value,inv-idx) u64 keys,
// 16 leaders STS into parity-double-buffered wred, ONE __syncthreads, then
// EVERY warp redundantly butterflies the 16 entries -> all lanes hold the
// winner. No atomics, no second barrier.
#define FPS_PT 16
__global__ void __launch_bounds__(512, 1)
fps_kernel(const float* __restrict__ p1, float* __restrict__ p2out) {
    extern __shared__ float sm[];
    float* px = sm; float* py = sm + NN; float* pz = sm + 2*NN;
    __shared__ unsigned long long wred[2][16];
    const int b = blockIdx.x;
    const int tid = threadIdx.x;
    const int lane = tid & 31;
    const int wid  = tid >> 5;
    const float* p = p1 + (size_t)b*NN*3;

    float MD[FPS_PT];
    unsigned long long Xp[FPS_PT/2], Yp[FPS_PT/2], Zp[FPS_PT/2];
    {
        float buf[FPS_PT*3];
        const float4* pv = (const float4*)(p + (size_t)tid*FPS_PT*3);
        #pragma unroll
        for (int i = 0; i < FPS_PT*3/4; i++) {
            float4 v = pv[i];
            buf[i*4+0]=v.x; buf[i*4+1]=v.y; buf[i*4+2]=v.z; buf[i*4+3]=v.w;
        }
        #pragma unroll
        for (int k = 0; k < FPS_PT; k++) {
            MD[k] = 1e10f;
            px[tid*FPS_PT+k]=buf[k*3]; py[tid*FPS_PT+k]=buf[k*3+1]; pz[tid*FPS_PT+k]=buf[k*3+2];
        }
        #pragma unroll
        for (int i = 0; i < FPS_PT/2; i++) {
            PACK_F32X2(Xp[i], buf[6*i+0], buf[6*i+3]);
            PACK_F32X2(Yp[i], buf[6*i+1], buf[6*i+4]);
            PACK_F32X2(Zp[i], buf[6*i+2], buf[6*i+5]);
        }
    }
    if (tid == 0) {
        size_t o0 = (size_t)b*MM*3;
        p2out[o0+0]=p[0]; p2out[o0+1]=p[1]; p2out[o0+2]=p[2];
    }
    __syncthreads();
    float lx = px[0], ly = py[0], lz = pz[0];

    for (int j = 1; j < MM; j++) {
        float nlx = -lx, nly = -ly, nlz = -lz;
        unsigned long long nlx2, nly2, nlz2;
        PACK_F32X2(nlx2, nlx, nlx);
        PACK_F32X2(nly2, nly, nly);
        PACK_F32X2(nlz2, nlz, nlz);

        #pragma unroll
        for (int i = 0; i < FPS_PT/2; i++) {
            unsigned long long dx, dy, dz, sx, sy, sz, s, d;
            ADD_F32X2(dx, Xp[i], nlx2);          // X + (-lx) == X - lx (bitwise)
            ADD_F32X2(dy, Yp[i], nly2);
            ADD_F32X2(dz, Zp[i], nlz2);
            MUL_F32X2(sx, dx, dx);
            MUL_F32X2(sy, dy, dy);
            MUL_F32X2(sz, dz, dz);
            ADD_F32X2(s,  sx, sy);               // (dx^2+dy^2)
            ADD_F32X2(d,  s,  sz);               // ... + dz^2
            float d0, d1; UNPACK_F32X2(d0, d1, d);
            MD[2*i]   = fminf(MD[2*i],   d0);
            MD[2*i+1] = fminf(MD[2*i+1], d1);
        }

        // thread-local argmax: max tree, then lowest matching k
        float bv = MD[0];
        #pragma unroll
        for (int k = 1; k < FPS_PT; k++) bv = fmaxf(bv, MD[k]);
        int bi = FPS_PT-1;
        #pragma unroll
        for (int k = FPS_PT-2; k >= 0; k--) if (MD[k] == bv) bi = k;

        // packed key: max value wins, tie -> lowest global index
        unsigned long long key =
            ((unsigned long long)__float_as_uint(bv) << 32) | (unsigned)(NN-1-(tid*FPS_PT+bi));
        #pragma unroll
        for (int o = 16; o; o >>= 1) {
            unsigned long long t = __shfl_xor_sync(0xffffffffu, key, o);
            if (t > key) key = t;
        }
        if (lane == 0) wred[j & 1][wid] = key;
        __syncthreads();

        // every warp redundantly reduces the 16 leader keys
        unsigned long long k2 = wred[j & 1][lane & 15];
        #pragma unroll
        for (int o = 8; o; o >>= 1) {
            unsigned long long t = __shfl_xor_sync(0xffffffffu, k2, o);
            if (t > k2) k2 = t;
        }
        int idx = (NN-1) - (int)(k2 & 0xffffffffu);
        if (tid == 0) {
            size_t o2 = (size_t)(b*MM + j)*3;
            p2out[o2]=px[idx]; p2out[o2+1]=py[idx]; p2out[o2+2]=pz[idx];
        }
        lx = px[idx]; ly = py[idx]; lz = pz[idx];
    }
}

// =============================== GEMM ===============================
// h[r][o] = sum_c x[r][c]*W[o][c], exact fp32, k-ascending FFMA chain from a
// zero accumulator — bit-matches cuBLAS SGEMM's inner loop.
__global__ void __launch_bounds__(256)
gemm_kernel(const float* __restrict__ x, const float* __restrict__ W) {
    extern __shared__ float sm[];
    float* xs = sm;                // [128][65] padded
    float* ws = sm + 128*65;       // [64][128] = W^T
    const int tid = threadIdx.x;
    const size_t rb = (size_t)blockIdx.x * 128;
    const float* gx = x + rb*CIN;

    for (int i = tid; i < 128*CIN; i += 256) {
        int r = i >> 6, c = i & 63;
        xs[r*65 + c] = gx[i];
    }
    for (int i = tid; i < COUT*CIN; i += 256) {
        int o = i >> 6, c = i & 63;
        ws[c*COUT + o] = W[i];
    }
    __syncthreads();

    const int tx = tid & 15, ty = tid >> 4;
    const int r0 = ty*8, o0 = tx*8;
    float acc[8][8];
    #pragma unroll
    for (int i = 0; i < 8; i++)
        #pragma unroll
        for (int j = 0; j < 8; j++) acc[i][j] = 0.f;

    for (int c = 0; c < CIN; c++) {
        float a[8];
        #pragma unroll
        for (int i = 0; i < 8; i++) a[i] = xs[(r0+i)*65 + c];
        float4 b0 = *(const float4*)&ws[c*COUT + o0];
        float4 b1 = *(const float4*)&ws[c*COUT + o0 + 4];
        float bb[8] = {b0.x,b0.y,b0.z,b0.w,b1.x,b1.y,b1.z,b1.w};
        #pragma unroll
        for (int i = 0; i < 8; i++)
            #pragma unroll
            for (int j = 0; j < 8; j++) acc[i][j] = __fmaf_rn(a[i], bb[j], acc[i][j]);
    }
    #pragma unroll
    for (int i = 0; i < 8; i++) {
        float* out = &g_h[(rb + r0 + i)*COUT + o0];
        *(float4*)out       = make_float4(acc[i][0],acc[i][1],acc[i][2],acc[i][3]);
        *(float4*)(out + 4) = make_float4(acc[i][4],acc[i][5],acc[i][6],acc[i][7]);
    }
}

// ====================== BN stats (deterministic 2-stage) ======================
__global__ void __launch_bounds__(128) bnstat1() {
    const int c = threadIdx.x;
    const int blk = blockIdx.x;                  // 256 blocks x 256 rows
    const float* base = g_h + (size_t)blk*256*COUT;
    float s = 0.f, q = 0.f;
    for (int r = 0; r < 256; r++) {
        float v = base[(size_t)r*COUT + c];
        s += v; q = __fmaf_rn(v, v, q);
    }
    g_psum[blk*COUT + c] = s;
    g_psq [blk*COUT + c] = q;
}

// one block per channel; 256 threads each grab one partial, warp+smem tree
__global__ void __launch_bounds__(256)
bnstat2(const float* __restrict__ gamma, const float* __restrict__ beta) {
    const int c = blockIdx.x;
    const int t = threadIdx.x;
    __shared__ double ss[8], sq[8];
    double s = (double)g_psum[t*COUT + c];
    double q = (double)g_psq [t*COUT + c];
    #pragma unroll
    for (int o = 16; o; o >>= 1) {
        s += __shfl_down_sync(0xffffffffu, s, o);
        q += __shfl_down_sync(0xffffffffu, q, o);
    }
    if ((t & 31) == 0) { ss[t >> 5] = s; sq[t >> 5] = q; }
    __syncthreads();
    if (t == 0) {
        double S = 0.0, Q = 0.0;
        #pragma unroll
        for (int w = 0; w < 8; w++) { S += ss[w]; Q += sq[w]; }
        double mean = S / (double)ROWS;
        double var  = Q / (double)ROWS - mean*mean;
        double inv  = 1.0 / sqrt(var + 1e-5);
        float sc = (float)inv * gamma[c];
        g_scale[c] = sc;
        g_shift[c] = __fmaf_rn(-(float)mean, sc, beta[c]);
    }
}

// =============================== kNN ===============================
// One warp per query. Per-lane register top-16 (packed sortable keys),
// warp merge by 16x min-extraction.
// d2 = (s2 - 2*dot) + s1 with:
//   s1, s2 : separate rn mul/add  (XLA fused elementwise+reduce — no FMA)
//   dot    : FFMA chain, k-ascending from rn(x*qx)  (cuBLAS SGEMM inner loop)
__device__ __forceinline__ unsigned f2key(float d) {
    unsigned u = __float_as_uint(d);
    return u ^ ((u >> 31) ? 0xFFFFFFFFu : 0x80000000u);
}

__global__ void __launch_bounds__(256)
knn_kernel(const float* __restrict__ p1, const float* __restrict__ p2) {
    extern __shared__ float sm[];
    float* px = sm; float* py = sm+NN; float* pz = sm+2*NN; float* s1 = sm+3*NN;
    const int tid = threadIdx.x;
    const int b  = blockIdx.x >> 8;       // 256 blocks per batch
    const int mg = blockIdx.x & 255;
    const float* p = p1 + (size_t)b*NN*3;

    for (int i = tid; i < NN*3; i += 256) {
        float v = p[i];
        int pt = i / 3, d = i - pt*3;
        (d == 0 ? px : (d == 1 ? py : pz))[pt] = v;
    }
    __syncthreads();
    for (int i = tid; i < NN; i += 256)
        s1[i] = __fadd_rn(__fadd_rn(__fmul_rn(px[i],px[i]), __fmul_rn(py[i],py[i])), __fmul_rn(pz[i],pz[i]));
    __syncthreads();

    const int w = tid >> 5, lane = tid & 31;
    const int m = mg*8 + w;
    const size_t qi = (size_t)b*MM + m;
    const float qx = p2[qi*3], qy = p2[qi*3+1], qz = p2[qi*3+2];
    const float s2 = __fadd_rn(__fadd_rn(__fmul_rn(qx,qx), __fmul_rn(qy,qy)), __fmul_rn(qz,qz));

    const unsigned long long INITK =
        ((unsigned long long)0xFF7FFFFFu << 32) | 0xFFFFFFFFu;
    unsigned long long bk[KNN];
    #pragma unroll
    for (int k = 0; k < KNN; k++) bk[k] = INITK;
    float thr = 3.4e38f;

    for (int i = lane; i < NN; i += 32) {
        float dot = __fmaf_rn(pz[i], qz, __fmaf_rn(py[i], qy, __fmul_rn(px[i], qx)));
        float d   = __fadd_rn(__fsub_rn(s2, __fmul_rn(2.0f, dot)), s1[i]);
        if (d < thr) {   // equal -> keep earlier index (top_k stability)
            unsigned long long nk = ((unsigned long long)f2key(d) << 32) | (unsigned)i;
            unsigned long long mk = 0; int mp = 0;
            #pragma unroll
            for (int k = 0; k < KNN; k++) if (bk[k] > mk) { mk = bk[k]; mp = k; }
            #pragma unroll
            for (int k = 0; k < KNN; k++) if (k == mp) bk[k] = nk;
            mk = 0;
            #pragma unroll
            for (int k = 0; k < KNN; k++) if (bk[k] > mk) mk = bk[k];
            unsigned hv = (unsigned)(mk >> 32);
            hv = (hv & 0x80000000u) ? (hv ^ 0x80000000u) : ~hv;
            thr = __uint_as_float(hv);
        }
    }

    unsigned long long res = 0;
    for (int r = 0; r < KNN; r++) {
        unsigned long long lm = 0xFFFFFFFFFFFFFFFFull;
        #pragma unroll
        for (int k = 0; k < KNN; k++) if (bk[k] < lm) lm = bk[k];
        unsigned long long wm = lm;
        #pragma unroll
        for (int o = 16; o; o >>= 1) {
            unsigned long long t = __shfl_xor_sync(0xffffffffu, wm, o);
            if (t < wm) wm = t;
        }
        if (lm == wm) {
            #pragma unroll
            for (int k = 0; k < KNN; k++) if (bk[k] == wm) bk[k] = 0xFFFFFFFFFFFFFFFFull;
        }
        if (lane == r) res = wm;
    }
    if (lane < KNN) g_nbr[qi*KNN + lane] = (int)(res & 0xFFFFFFFFu);
}

// =========================== gather + BN + ReLU + max ===========================
__global__ void __launch_bounds__(256)
gather_kernel(float* __restrict__ y) {
    const int tid = threadIdx.x;
    const int w = tid >> 5, lane = tid & 31;
    const int q = blockIdx.x*8 + w;              // global (b,m) id
    const int b = q >> 11;
    const int* nb = g_nbr + (size_t)q*KNN;
    const float4 sc = *(const float4*)&g_scale[lane*4];
    const float4 sh = *(const float4*)&g_shift[lane*4];
    const float* hb = g_h + (size_t)b*NN*COUT;

    float4 acc = make_float4(-3.4e38f,-3.4e38f,-3.4e38f,-3.4e38f);
    #pragma unroll
    for (int k = 0; k < KNN; k++) {
        int n = nb[k];
        float4 v = *(const float4*)&hb[(size_t)n*COUT + lane*4];
        float f;
        f = fmaxf(__fmaf_rn(v.x, sc.x, sh.x), 0.f); acc.x = fmaxf(acc.x, f);
        f = fmaxf(__fmaf_rn(v.y, sc.y, sh.y), 0.f); acc.y = fmaxf(acc.y, f);
        f = fmaxf(__fmaf_rn(v.z, sc.z, sh.z), 0.f); acc.z = fmaxf(acc.z, f);
        f = fmaxf(__fmaf_rn(v.w, sc.w, sh.w), 0.f); acc.w = fmaxf(acc.w, f);
    }
    *(float4*)&y[(size_t)q*COUT + lane*4] = acc;
}

// =============================== launch ===============================
extern "C" void kernel_launch(void* const* d_in, const int* in_sizes, int n_in,
                              void* d_out, int out_size) {
    const float* x     = (const float*)d_in[0];
    const float* p1    = (const float*)d_in[1];
    const float* W     = (const float*)d_in[2];
    const float* gamma = (const float*)d_in[3];
    const float* beta  = (const float*)d_in[4];
    float* y  = (float*)d_out;
    float* p2 = y + Y_SIZE;

    const int FPS_SMEM  = 3*NN*4;          // 96 KB
    const int KNN_SMEM  = 4*NN*4;          // 128 KB
    const int GEMM_SMEM = (128*65 + 64*128)*4;

    cudaFuncSetAttribute(fps_kernel,  cudaFuncAttributeMaxDynamicSharedMemorySize, FPS_SMEM);
    cudaFuncSetAttribute(knn_kernel,  cudaFuncAttributeMaxDynamicSharedMemorySize, KNN_SMEM);
    cudaFuncSetAttribute(gemm_kernel, cudaFuncAttributeMaxDynamicSharedMemorySize, GEMM_SMEM);

    fps_kernel<<<BB, 512, FPS_SMEM>>>(p1, p2);
    gemm_kernel<<<ROWS/128, 256, GEMM_SMEM>>>(x, W);
    bnstat1<<<256, 128>>>();
    bnstat2<<<COUT, 256>>>(gamma, beta);
    knn_kernel<<<BB*(MM/8), 256, KNN_SMEM>>>(p1, p2);
    gather_kernel<<<(BB*MM)/8, 256>>>(y);
}

// round 6
// speedup vs baseline: 1.2109x; 1.0562x over previous
#include <cuda_runtime.h>
#include <stdint.h>

#define BB   8
#define NN   8192
#define CIN  64
#define COUT 128
#define MM   2048
#define KNN  16
#define ROWS (BB*NN)            // 65536
#define Y_SIZE ((size_t)BB*MM*COUT)

// ---------------- scratch (static device globals; no allocations) ----------------
__device__ float g_h[(size_t)ROWS*COUT];     // raw h = x @ W^T  (32 MB)
__device__ int   g_nbr[(size_t)BB*MM*KNN];   // kNN indices
__device__ float g_psum[256*COUT];
__device__ float g_psq [256*COUT];
__device__ float g_scale[COUT];
__device__ float g_shift[COUT];

// -------- packed f32x2 helpers (sm_100+; per-lane bits == scalar rn ops) --------
#define ADD_F32X2(out, a, b) \
    asm("add.rn.f32x2 %0, %1, %2;" : "=l"(out) : "l"(a), "l"(b))
#define MUL_F32X2(out, a, b) \
    asm("mul.rn.f32x2 %0, %1, %2;" : "=l"(out) : "l"(a), "l"(b))
#define PACK_F32X2(out, lo, hi) \
    asm("mov.b64 %0, {%1, %2};" : "=l"(out) : "f"(lo), "f"(hi))
#define UNPACK_F32X2(lo, hi, in) \
    asm("mov.b64 {%0, %1}, %2;" : "=f"(lo), "=f"(hi) : "l"(in))

#define REDUX_MAX_U32(out, in) \
    asm("redux.sync.max.u32 %0, %1, 0xffffffff;" : "=r"(out) : "r"(in))

// =============================== FPS ===============================
// One block per batch, 512 threads, 16 points/thread in registers.
// Distance math: packed f32x2 with the exact scalar rounding pattern
// dx=X+(-lx), d=(dx^2+dy^2)+dz^2 — bit-identical to XLA (trajectory verified).
// Reduction: distances >= 0 so float order == u32 order. Per warp:
// redux.sync.max.u32 + ballot + one shfl (lowest lane = lowest index).
// Cross-warp: 16 leader (val,idx) slots, ONE __syncthreads, then every warp
// does LDS + redux + ballot (lowest slot = lowest index). Parity double-buffer.
#define FPS_PT 16
__global__ void __launch_bounds__(512, 1)
fps_kernel(const float* __restrict__ p1, float* __restrict__ p2out) {
    extern __shared__ float sm[];
    float* px = sm; float* py = sm + NN; float* pz = sm + 2*NN;
    __shared__ unsigned wval[2][16];
    __shared__ int      widxs[2][16];
    const int b = blockIdx.x;
    const int tid = threadIdx.x;
    const int lane = tid & 31;
    const int wid  = tid >> 5;
    const float* p = p1 + (size_t)b*NN*3;

    float MD[FPS_PT];
    unsigned long long Xp[FPS_PT/2], Yp[FPS_PT/2], Zp[FPS_PT/2];
    {
        float buf[FPS_PT*3];
        const float4* pv = (const float4*)(p + (size_t)tid*FPS_PT*3);
        #pragma unroll
        for (int i = 0; i < FPS_PT*3/4; i++) {
            float4 v = pv[i];
            buf[i*4+0]=v.x; buf[i*4+1]=v.y; buf[i*4+2]=v.z; buf[i*4+3]=v.w;
        }
        #pragma unroll
        for (int k = 0; k < FPS_PT; k++) {
            MD[k] = 1e10f;
            px[tid*FPS_PT+k]=buf[k*3]; py[tid*FPS_PT+k]=buf[k*3+1]; pz[tid*FPS_PT+k]=buf[k*3+2];
        }
        #pragma unroll
        for (int i = 0; i < FPS_PT/2; i++) {
            PACK_F32X2(Xp[i], buf[6*i+0], buf[6*i+3]);
            PACK_F32X2(Yp[i], buf[6*i+1], buf[6*i+4]);
            PACK_F32X2(Zp[i], buf[6*i+2], buf[6*i+5]);
        }
    }
    if (tid == 0) {
        size_t o0 = (size_t)b*MM*3;
        p2out[o0+0]=p[0]; p2out[o0+1]=p[1]; p2out[o0+2]=p[2];
    }
    __syncthreads();
    float lx = px[0], ly = py[0], lz = pz[0];

    for (int j = 1; j < MM; j++) {
        float nlx = -lx, nly = -ly, nlz = -lz;
        unsigned long long nlx2, nly2, nlz2;
        PACK_F32X2(nlx2, nlx, nlx);
        PACK_F32X2(nly2, nly, nly);
        PACK_F32X2(nlz2, nlz, nlz);

        #pragma unroll
        for (int i = 0; i < FPS_PT/2; i++) {
            unsigned long long dx, dy, dz, sx, sy, sz, s, d;
            ADD_F32X2(dx, Xp[i], nlx2);          // X + (-lx) == X - lx (bitwise)
            ADD_F32X2(dy, Yp[i], nly2);
            ADD_F32X2(dz, Zp[i], nlz2);
            MUL_F32X2(sx, dx, dx);
            MUL_F32X2(sy, dy, dy);
            MUL_F32X2(sz, dz, dz);
            ADD_F32X2(s,  sx, sy);               // (dx^2+dy^2)
            ADD_F32X2(d,  s,  sz);               // ... + dz^2
            float d0, d1; UNPACK_F32X2(d0, d1, d);
            MD[2*i]   = fminf(MD[2*i],   d0);
            MD[2*i+1] = fminf(MD[2*i+1], d1);
        }

        // thread-local argmax: max tree, then lowest matching k
        float bv = MD[0];
        #pragma unroll
        for (int k = 1; k < FPS_PT; k++) bv = fmaxf(bv, MD[k]);
        int bi = FPS_PT-1;
        #pragma unroll
        for (int k = FPS_PT-2; k >= 0; k--) if (MD[k] == bv) bi = k;
        int gbi = tid*FPS_PT + bi;

        // warp argmax: distances >= 0 -> float order == u32 order.
        // lowest set lane == lowest global index (lanes cover ascending ranges).
        unsigned bvb = __float_as_uint(bv);
        unsigned wmax; REDUX_MAX_U32(wmax, bvb);
        unsigned ball = __ballot_sync(0xffffffffu, bvb == wmax);
        int src = __ffs(ball) - 1;
        int wbi = __shfl_sync(0xffffffffu, gbi, src);
        if (lane == 0) { wval[j & 1][wid] = wmax; widxs[j & 1][wid] = wbi; }
        __syncthreads();

        // cross-warp: every warp redundantly reduces the 16 leader values
        unsigned v = wval[j & 1][lane & 15];
        unsigned gmax; REDUX_MAX_U32(gmax, v);
        unsigned b2 = __ballot_sync(0xffffffffu, v == gmax) & 0xffffu;
        int slot = __ffs(b2) - 1;                  // lowest slot = lowest index
        int idx = widxs[j & 1][slot];              // LDS broadcast
        if (tid == 0) {
            size_t o2 = (size_t)(b*MM + j)*3;
            p2out[o2]=px[idx]; p2out[o2+1]=py[idx]; p2out[o2+2]=pz[idx];
        }
        lx = px[idx]; ly = py[idx]; lz = pz[idx];
    }
}

// =============================== GEMM ===============================
// h[r][o] = sum_c x[r][c]*W[o][c], exact fp32, k-ascending FFMA chain from a
// zero accumulator — bit-matches cuBLAS SGEMM's inner loop.
__global__ void __launch_bounds__(256)
gemm_kernel(const float* __restrict__ x, const float* __restrict__ W) {
    extern __shared__ float sm[];
    float* xs = sm;                // [128][65] padded
    float* ws = sm + 128*65;       // [64][128] = W^T
    const int tid = threadIdx.x;
    const size_t rb = (size_t)blockIdx.x * 128;
    const float* gx = x + rb*CIN;

    for (int i = tid; i < 128*CIN; i += 256) {
        int r = i >> 6, c = i & 63;
        xs[r*65 + c] = gx[i];
    }
    for (int i = tid; i < COUT*CIN; i += 256) {
        int o = i >> 6, c = i & 63;
        ws[c*COUT + o] = W[i];
    }
    __syncthreads();

    const int tx = tid & 15, ty = tid >> 4;
    const int r0 = ty*8, o0 = tx*8;
    float acc[8][8];
    #pragma unroll
    for (int i = 0; i < 8; i++)
        #pragma unroll
        for (int j = 0; j < 8; j++) acc[i][j] = 0.f;

    for (int c = 0; c < CIN; c++) {
        float a[8];
        #pragma unroll
        for (int i = 0; i < 8; i++) a[i] = xs[(r0+i)*65 + c];
        float4 b0 = *(const float4*)&ws[c*COUT + o0];
        float4 b1 = *(const float4*)&ws[c*COUT + o0 + 4];
        float bb[8] = {b0.x,b0.y,b0.z,b0.w,b1.x,b1.y,b1.z,b1.w};
        #pragma unroll
        for (int i = 0; i < 8; i++)
            #pragma unroll
            for (int j = 0; j < 8; j++) acc[i][j] = __fmaf_rn(a[i], bb[j], acc[i][j]);
    }
    #pragma unroll
    for (int i = 0; i < 8; i++) {
        float* out = &g_h[(rb + r0 + i)*COUT + o0];
        *(float4*)out       = make_float4(acc[i][0],acc[i][1],acc[i][2],acc[i][3]);
        *(float4*)(out + 4) = make_float4(acc[i][4],acc[i][5],acc[i][6],acc[i][7]);
    }
}

// ====================== BN stats (deterministic 2-stage) ======================
__global__ void __launch_bounds__(128) bnstat1() {
    const int c = threadIdx.x;
    const int blk = blockIdx.x;                  // 256 blocks x 256 rows
    const float* base = g_h + (size_t)blk*256*COUT;
    float s = 0.f, q = 0.f;
    for (int r = 0; r < 256; r++) {
        float v = base[(size_t)r*COUT + c];
        s += v; q = __fmaf_rn(v, v, q);
    }
    g_psum[blk*COUT + c] = s;
    g_psq [blk*COUT + c] = q;
}

// one block per channel; 256 threads each grab one partial, warp+smem tree
__global__ void __launch_bounds__(256)
bnstat2(const float* __restrict__ gamma, const float* __restrict__ beta) {
    const int c = blockIdx.x;
    const int t = threadIdx.x;
    __shared__ double ss[8], sq[8];
    double s = (double)g_psum[t*COUT + c];
    double q = (double)g_psq [t*COUT + c];
    #pragma unroll
    for (int o = 16; o; o >>= 1) {
        s += __shfl_down_sync(0xffffffffu, s, o);
        q += __shfl_down_sync(0xffffffffu, q, o);
    }
    if ((t & 31) == 0) { ss[t >> 5] = s; sq[t >> 5] = q; }
    __syncthreads();
    if (t == 0) {
        double S = 0.0, Q = 0.0;
        #pragma unroll
        for (int w = 0; w < 8; w++) { S += ss[w]; Q += sq[w]; }
        double mean = S / (double)ROWS;
        double var  = Q / (double)ROWS - mean*mean;
        double inv  = 1.0 / sqrt(var + 1e-5);
        float sc = (float)inv * gamma[c];
        g_scale[c] = sc;
        g_shift[c] = __fmaf_rn(-(float)mean, sc, beta[c]);
    }
}

// =============================== kNN ===============================
// One warp per query. Per-lane register top-16 (packed sortable keys),
// warp merge by 16x min-extraction.
// d2 = (s2 - 2*dot) + s1 with:
//   s1, s2 : separate rn mul/add  (XLA fused elementwise+reduce — no FMA)
//   dot    : FFMA chain, k-ascending from rn(x*qx)  (cuBLAS SGEMM inner loop)
__device__ __forceinline__ unsigned f2key(float d) {
    unsigned u = __float_as_uint(d);
    return u ^ ((u >> 31) ? 0xFFFFFFFFu : 0x80000000u);
}

__global__ void __launch_bounds__(256)
knn_kernel(const float* __restrict__ p1, const float* __restrict__ p2) {
    extern __shared__ float sm[];
    float* px = sm; float* py = sm+NN; float* pz = sm+2*NN; float* s1 = sm+3*NN;
    const int tid = threadIdx.x;
    const int b  = blockIdx.x >> 8;       // 256 blocks per batch
    const int mg = blockIdx.x & 255;
    const float* p = p1 + (size_t)b*NN*3;

    for (int i = tid; i < NN*3; i += 256) {
        float v = p[i];
        int pt = i / 3, d = i - pt*3;
        (d == 0 ? px : (d == 1 ? py : pz))[pt] = v;
    }
    __syncthreads();
    for (int i = tid; i < NN; i += 256)
        s1[i] = __fadd_rn(__fadd_rn(__fmul_rn(px[i],px[i]), __fmul_rn(py[i],py[i])), __fmul_rn(pz[i],pz[i]));
    __syncthreads();

    const int w = tid >> 5, lane = tid & 31;
    const int m = mg*8 + w;
    const size_t qi = (size_t)b*MM + m;
    const float qx = p2[qi*3], qy = p2[qi*3+1], qz = p2[qi*3+2];
    const float s2 = __fadd_rn(__fadd_rn(__fmul_rn(qx,qx), __fmul_rn(qy,qy)), __fmul_rn(qz,qz));

    const unsigned long long INITK =
        ((unsigned long long)0xFF7FFFFFu << 32) | 0xFFFFFFFFu;
    unsigned long long bk[KNN];
    #pragma unroll
    for (int k = 0; k < KNN; k++) bk[k] = INITK;
    float thr = 3.4e38f;

    for (int i = lane; i < NN; i += 32) {
        float dot = __fmaf_rn(pz[i], qz, __fmaf_rn(py[i], qy, __fmul_rn(px[i], qx)));
        float d   = __fadd_rn(__fsub_rn(s2, __fmul_rn(2.0f, dot)), s1[i]);
        if (d < thr) {   // equal -> keep earlier index (top_k stability)
            unsigned long long nk = ((unsigned long long)f2key(d) << 32) | (unsigned)i;
            unsigned long long mk = 0; int mp = 0;
            #pragma unroll
            for (int k = 0; k < KNN; k++) if (bk[k] > mk) { mk = bk[k]; mp = k; }
            #pragma unroll
            for (int k = 0; k < KNN; k++) if (k == mp) bk[k] = nk;
            mk = 0;
            #pragma unroll
            for (int k = 0; k < KNN; k++) if (bk[k] > mk) mk = bk[k];
            unsigned hv = (unsigned)(mk >> 32);
            hv = (hv & 0x80000000u) ? (hv ^ 0x80000000u) : ~hv;
            thr = __uint_as_float(hv);
        }
    }

    unsigned long long res = 0;
    for (int r = 0; r < KNN; r++) {
        unsigned long long lm = 0xFFFFFFFFFFFFFFFFull;
        #pragma unroll
        for (int k = 0; k < KNN; k++) if (bk[k] < lm) lm = bk[k];
        unsigned long long wm = lm;
        #pragma unroll
        for (int o = 16; o; o >>= 1) {
            unsigned long long t = __shfl_xor_sync(0xffffffffu, wm, o);
            if (t < wm) wm = t;
        }
        if (lm == wm) {
            #pragma unroll
            for (int k = 0; k < KNN; k++) if (bk[k] == wm) bk[k] = 0xFFFFFFFFFFFFFFFFull;
        }
        if (lane == r) res = wm;
    }
    if (lane < KNN) g_nbr[qi*KNN + lane] = (int)(res & 0xFFFFFFFFu);
}

// =========================== gather + BN + ReLU + max ===========================
__global__ void __launch_bounds__(256)
gather_kernel(float* __restrict__ y) {
    const int tid = threadIdx.x;
    const int w = tid >> 5, lane = tid & 31;
    const int q = blockIdx.x*8 + w;              // global (b,m) id
    const int b = q >> 11;
    const int* nb = g_nbr + (size_t)q*KNN;
    const float4 sc = *(const float4*)&g_scale[lane*4];
    const float4 sh = *(const float4*)&g_shift[lane*4];
    const float* hb = g_h + (size_t)b*NN*COUT;

    float4 acc = make_float4(-3.4e38f,-3.4e38f,-3.4e38f,-3.4e38f);
    #pragma unroll
    for (int k = 0; k < KNN; k++) {
        int n = nb[k];
        float4 v = *(const float4*)&hb[(size_t)n*COUT + lane*4];
        float f;
        f = fmaxf(__fmaf_rn(v.x, sc.x, sh.x), 0.f); acc.x = fmaxf(acc.x, f);
        f = fmaxf(__fmaf_rn(v.y, sc.y, sh.y), 0.f); acc.y = fmaxf(acc.y, f);
        f = fmaxf(__fmaf_rn(v.z, sc.z, sh.z), 0.f); acc.z = fmaxf(acc.z, f);
        f = fmaxf(__fmaf_rn(v.w, sc.w, sh.w), 0.f); acc.w = fmaxf(acc.w, f);
    }
    *(float4*)&y[(size_t)q*COUT + lane*4] = acc;
}

// =============================== launch ===============================
extern "C" void kernel_launch(void* const* d_in, const int* in_sizes, int n_in,
                              void* d_out, int out_size) {
    const float* x     = (const float*)d_in[0];
    const float* p1    = (const float*)d_in[1];
    const float* W     = (const float*)d_in[2];
    const float* gamma = (const float*)d_in[3];
    const float* beta  = (const float*)d_in[4];
    float* y  = (float*)d_out;
    float* p2 = y + Y_SIZE;

    const int FPS_SMEM  = 3*NN*4;          // 96 KB
    const int KNN_SMEM  = 4*NN*4;          // 128 KB
    const int GEMM_SMEM = (128*65 + 64*128)*4;

    cudaFuncSetAttribute(fps_kernel,  cudaFuncAttributeMaxDynamicSharedMemorySize, FPS_SMEM);
    cudaFuncSetAttribute(knn_kernel,  cudaFuncAttributeMaxDynamicSharedMemorySize, KNN_SMEM);
    cudaFuncSetAttribute(gemm_kernel, cudaFuncAttributeMaxDynamicSharedMemorySize, GEMM_SMEM);

    fps_kernel<<<BB, 512, FPS_SMEM>>>(p1, p2);
    gemm_kernel<<<ROWS/128, 256, GEMM_SMEM>>>(x, W);
    bnstat1<<<256, 128>>>();
    bnstat2<<<COUT, 256>>>(gamma, beta);
    knn_kernel<<<BB*(MM/8), 256, KNN_SMEM>>>(p1, p2);
    gather_kernel<<<(BB*MM)/8, 256>>>(y);
}

// round 7
// speedup vs baseline: 1.2370x; 1.0216x over previous
#include <cuda_runtime.h>
#include <stdint.h>

#define BB   8
#define NN   8192
#define CIN  64
#define COUT 128
#define MM   2048
#define KNN  16
#define ROWS (BB*NN)            // 65536
#define Y_SIZE ((size_t)BB*MM*COUT)

// ---------------- scratch (static device globals; no allocations) ----------------
__device__ float g_h[(size_t)ROWS*COUT];     // raw h = x @ W^T  (32 MB)
__device__ int   g_nbr[(size_t)BB*MM*KNN];   // kNN indices
__device__ float g_psum[256*COUT];
__device__ float g_psq [256*COUT];
__device__ float g_scale[COUT];
__device__ float g_shift[COUT];

// -------- packed f32x2 helpers (sm_100+; per-lane bits == scalar rn ops) --------
#define ADD_F32X2(out, a, b) \
    asm("add.rn.f32x2 %0, %1, %2;" : "=l"(out) : "l"(a), "l"(b))
#define MUL_F32X2(out, a, b) \
    asm("mul.rn.f32x2 %0, %1, %2;" : "=l"(out) : "l"(a), "l"(b))
#define PACK_F32X2(out, lo, hi) \
    asm("mov.b64 %0, {%1, %2};" : "=l"(out) : "f"(lo), "f"(hi))
#define UNPACK_F32X2(lo, hi, in) \
    asm("mov.b64 {%0, %1}, %2;" : "=f"(lo), "=f"(hi) : "l"(in))

#define REDUX_MAX_U32(out, in) \
    asm("redux.sync.max.u32 %0, %1, 0xffffffff;" : "=r"(out) : "r"(in))

// =============================== FPS ===============================
// One block per batch, 512 threads, 16 points/thread in registers (packed
// f32x2). No positions array in smem: the winning lane broadcasts the winner
// coords from its own registers. Distance bits identical to XLA:
// dx=X+(-lx), d=(dx^2+dy^2)+dz^2, separate rn ops (trajectory bit-exact).
// Per iteration: per-warp redux.max.u32; leaders post to wval[]; bar1;
// all warps redux over the 16 leader values -> gmax + lowest winning slot;
// ONLY the winning warp resolves lane (ballot, lowest lane = lowest index)
// and that lane scans its 16 dists (unrolled, static) for the lowest k,
// writes coords to the bcast slot + p2out; bar2; everyone reads bcast.
#define FPS_PT 16
__global__ void __launch_bounds__(512, 1)
fps_kernel(const float* __restrict__ p1, float* __restrict__ p2out) {
    __shared__ unsigned wval[16];
    __shared__ float bc[3];
    const int b = blockIdx.x;
    const int tid = threadIdx.x;
    const int lane = tid & 31;
    const int wid  = tid >> 5;
    const float* p = p1 + (size_t)b*NN*3;

    float MD[FPS_PT];
    unsigned long long Xp[FPS_PT/2], Yp[FPS_PT/2], Zp[FPS_PT/2];
    {
        float buf[FPS_PT*3];
        const float4* pv = (const float4*)(p + (size_t)tid*FPS_PT*3);
        #pragma unroll
        for (int i = 0; i < FPS_PT*3/4; i++) {
            float4 v = pv[i];
            buf[i*4+0]=v.x; buf[i*4+1]=v.y; buf[i*4+2]=v.z; buf[i*4+3]=v.w;
        }
        #pragma unroll
        for (int k = 0; k < FPS_PT; k++) MD[k] = 1e10f;
        #pragma unroll
        for (int i = 0; i < FPS_PT/2; i++) {
            PACK_F32X2(Xp[i], buf[6*i+0], buf[6*i+3]);
            PACK_F32X2(Yp[i], buf[6*i+1], buf[6*i+4]);
            PACK_F32X2(Zp[i], buf[6*i+2], buf[6*i+5]);
        }
    }
    float lx = p[0], ly = p[1], lz = p[2];   // broadcast const-cached load
    if (tid == 0) {
        size_t o0 = (size_t)b*MM*3;
        p2out[o0+0]=lx; p2out[o0+1]=ly; p2out[o0+2]=lz;
    }

    for (int j = 1; j < MM; j++) {
        float nlx = -lx, nly = -ly, nlz = -lz;
        unsigned long long nlx2, nly2, nlz2;
        PACK_F32X2(nlx2, nlx, nlx);
        PACK_F32X2(nly2, nly, nly);
        PACK_F32X2(nlz2, nlz, nlz);

        #pragma unroll
        for (int i = 0; i < FPS_PT/2; i++) {
            unsigned long long dx, dy, dz, sx, sy, sz, s, d;
            ADD_F32X2(dx, Xp[i], nlx2);          // X + (-lx) == X - lx (bitwise)
            ADD_F32X2(dy, Yp[i], nly2);
            ADD_F32X2(dz, Zp[i], nlz2);
            MUL_F32X2(sx, dx, dx);
            MUL_F32X2(sy, dy, dy);
            MUL_F32X2(sz, dz, dz);
            ADD_F32X2(s,  sx, sy);               // (dx^2+dy^2)
            ADD_F32X2(d,  s,  sz);               // ... + dz^2
            float d0, d1; UNPACK_F32X2(d0, d1, d);
            MD[2*i]   = fminf(MD[2*i],   d0);
            MD[2*i+1] = fminf(MD[2*i+1], d1);
        }

        // thread-local max VALUE only (binary tree; index deferred)
        float t0 = fmaxf(MD[0],MD[1]),  t1 = fmaxf(MD[2],MD[3]);
        float t2 = fmaxf(MD[4],MD[5]),  t3 = fmaxf(MD[6],MD[7]);
        float t4 = fmaxf(MD[8],MD[9]),  t5 = fmaxf(MD[10],MD[11]);
        float t6 = fmaxf(MD[12],MD[13]),t7 = fmaxf(MD[14],MD[15]);
        t0 = fmaxf(t0,t1); t2 = fmaxf(t2,t3); t4 = fmaxf(t4,t5); t6 = fmaxf(t6,t7);
        float bv = fmaxf(fmaxf(t0,t2), fmaxf(t4,t6));

        // warp max (dist >= 0 -> float order == u32 order)
        unsigned bvb = __float_as_uint(bv);
        unsigned wmax; REDUX_MAX_U32(wmax, bvb);
        if (lane == 0) wval[wid] = wmax;
        __syncthreads();                               // bar1

        // all warps: block max over 16 leader values; lowest slot = lowest idx
        unsigned v = wval[lane & 15];
        unsigned gmax; REDUX_MAX_U32(gmax, v);
        unsigned b2 = __ballot_sync(0xffffffffu, v == gmax) & 0xffffu;
        int gslot = __ffs(b2) - 1;

        if (wid == gslot) {                            // only the winning warp
            unsigned mball = __ballot_sync(0xffffffffu, bvb == gmax);
            int wl = __ffs(mball) - 1;                 // lowest lane = lowest idx
            if (lane == wl) {
                // lowest k with MD[k]==gmax; select its coords (static idx)
                float cx = 0.f, cy = 0.f, cz = 0.f;
                #pragma unroll
                for (int k = FPS_PT-1; k >= 0; k--) {
                    if (__float_as_uint(MD[k]) == gmax) {
                        float a0, a1;
                        UNPACK_F32X2(a0, a1, Xp[k/2]); cx = (k & 1) ? a1 : a0;
                        UNPACK_F32X2(a0, a1, Yp[k/2]); cy = (k & 1) ? a1 : a0;
                        UNPACK_F32X2(a0, a1, Zp[k/2]); cz = (k & 1) ? a1 : a0;
                    }
                }
                bc[0] = cx; bc[1] = cy; bc[2] = cz;
                size_t o2 = (size_t)(b*MM + j)*3;
                p2out[o2] = cx; p2out[o2+1] = cy; p2out[o2+2] = cz;
            }
        }
        __syncthreads();                               // bar2
        lx = bc[0]; ly = bc[1]; lz = bc[2];
    }
}

// =============================== GEMM ===============================
// h[r][o] = sum_c x[r][c]*W[o][c], exact fp32, k-ascending FFMA chain from a
// zero accumulator — bit-matches cuBLAS SGEMM's inner loop.
__global__ void __launch_bounds__(256)
gemm_kernel(const float* __restrict__ x, const float* __restrict__ W) {
    extern __shared__ float sm[];
    float* xs = sm;                // [128][65] padded
    float* ws = sm + 128*65;       // [64][128] = W^T
    const int tid = threadIdx.x;
    const size_t rb = (size_t)blockIdx.x * 128;
    const float* gx = x + rb*CIN;

    for (int i = tid; i < 128*CIN; i += 256) {
        int r = i >> 6, c = i & 63;
        xs[r*65 + c] = gx[i];
    }
    for (int i = tid; i < COUT*CIN; i += 256) {
        int o = i >> 6, c = i & 63;
        ws[c*COUT + o] = W[i];
    }
    __syncthreads();

    const int tx = tid & 15, ty = tid >> 4;
    const int r0 = ty*8, o0 = tx*8;
    float acc[8][8];
    #pragma unroll
    for (int i = 0; i < 8; i++)
        #pragma unroll
        for (int j = 0; j < 8; j++) acc[i][j] = 0.f;

    for (int c = 0; c < CIN; c++) {
        float a[8];
        #pragma unroll
        for (int i = 0; i < 8; i++) a[i] = xs[(r0+i)*65 + c];
        float4 b0 = *(const float4*)&ws[c*COUT + o0];
        float4 b1 = *(const float4*)&ws[c*COUT + o0 + 4];
        float bb[8] = {b0.x,b0.y,b0.z,b0.w,b1.x,b1.y,b1.z,b1.w};
        #pragma unroll
        for (int i = 0; i < 8; i++)
            #pragma unroll
            for (int j = 0; j < 8; j++) acc[i][j] = __fmaf_rn(a[i], bb[j], acc[i][j]);
    }
    #pragma unroll
    for (int i = 0; i < 8; i++) {
        float* out = &g_h[(rb + r0 + i)*COUT + o0];
        *(float4*)out       = make_float4(acc[i][0],acc[i][1],acc[i][2],acc[i][3]);
        *(float4*)(out + 4) = make_float4(acc[i][4],acc[i][5],acc[i][6],acc[i][7]);
    }
}

// ====================== BN stats (deterministic 2-stage) ======================
__global__ void __launch_bounds__(128) bnstat1() {
    const int c = threadIdx.x;
    const int blk = blockIdx.x;                  // 256 blocks x 256 rows
    const float* base = g_h + (size_t)blk*256*COUT;
    float s = 0.f, q = 0.f;
    for (int r = 0; r < 256; r++) {
        float v = base[(size_t)r*COUT + c];
        s += v; q = __fmaf_rn(v, v, q);
    }
    g_psum[blk*COUT + c] = s;
    g_psq [blk*COUT + c] = q;
}

// one block per channel; 256 threads each grab one partial, warp+smem tree
__global__ void __launch_bounds__(256)
bnstat2(const float* __restrict__ gamma, const float* __restrict__ beta) {
    const int c = blockIdx.x;
    const int t = threadIdx.x;
    __shared__ double ss[8], sq[8];
    double s = (double)g_psum[t*COUT + c];
    double q = (double)g_psq [t*COUT + c];
    #pragma unroll
    for (int o = 16; o; o >>= 1) {
        s += __shfl_down_sync(0xffffffffu, s, o);
        q += __shfl_down_sync(0xffffffffu, q, o);
    }
    if ((t & 31) == 0) { ss[t >> 5] = s; sq[t >> 5] = q; }
    __syncthreads();
    if (t == 0) {
        double S = 0.0, Q = 0.0;
        #pragma unroll
        for (int w = 0; w < 8; w++) { S += ss[w]; Q += sq[w]; }
        double mean = S / (double)ROWS;
        double var  = Q / (double)ROWS - mean*mean;
        double inv  = 1.0 / sqrt(var + 1e-5);
        float sc = (float)inv * gamma[c];
        g_scale[c] = sc;
        g_shift[c] = __fmaf_rn(-(float)mean, sc, beta[c]);
    }
}

// =============================== kNN ===============================
// One warp per query. Per-lane register top-16 (packed sortable keys),
// warp merge by 16x min-extraction.
// d2 = (s2 - 2*dot) + s1 with:
//   s1, s2 : separate rn mul/add  (XLA fused elementwise+reduce — no FMA)
//   dot    : FFMA chain, k-ascending from rn(x*qx)  (cuBLAS SGEMM inner loop)
__device__ __forceinline__ unsigned f2key(float d) {
    unsigned u = __float_as_uint(d);
    return u ^ ((u >> 31) ? 0xFFFFFFFFu : 0x80000000u);
}

__global__ void __launch_bounds__(256)
knn_kernel(const float* __restrict__ p1, const float* __restrict__ p2) {
    extern __shared__ float sm[];
    float* px = sm; float* py = sm+NN; float* pz = sm+2*NN; float* s1 = sm+3*NN;
    const int tid = threadIdx.x;
    const int b  = blockIdx.x >> 8;       // 256 blocks per batch
    const int mg = blockIdx.x & 255;
    const float* p = p1 + (size_t)b*NN*3;

    for (int i = tid; i < NN*3; i += 256) {
        float v = p[i];
        int pt = i / 3, d = i - pt*3;
        (d == 0 ? px : (d == 1 ? py : pz))[pt] = v;
    }
    __syncthreads();
    for (int i = tid; i < NN; i += 256)
        s1[i] = __fadd_rn(__fadd_rn(__fmul_rn(px[i],px[i]), __fmul_rn(py[i],py[i])), __fmul_rn(pz[i],pz[i]));
    __syncthreads();

    const int w = tid >> 5, lane = tid & 31;
    const int m = mg*8 + w;
    const size_t qi = (size_t)b*MM + m;
    const float qx = p2[qi*3], qy = p2[qi*3+1], qz = p2[qi*3+2];
    const float s2 = __fadd_rn(__fadd_rn(__fmul_rn(qx,qx), __fmul_rn(qy,qy)), __fmul_rn(qz,qz));

    const unsigned long long INITK =
        ((unsigned long long)0xFF7FFFFFu << 32) | 0xFFFFFFFFu;
    unsigned long long bk[KNN];
    #pragma unroll
    for (int k = 0; k < KNN; k++) bk[k] = INITK;
    float thr = 3.4e38f;

    for (int i = lane; i < NN; i += 32) {
        float dot = __fmaf_rn(pz[i], qz, __fmaf_rn(py[i], qy, __fmul_rn(px[i], qx)));
        float d   = __fadd_rn(__fsub_rn(s2, __fmul_rn(2.0f, dot)), s1[i]);
        if (d < thr) {   // equal -> keep earlier index (top_k stability)
            unsigned long long nk = ((unsigned long long)f2key(d) << 32) | (unsigned)i;
            unsigned long long mk = 0; int mp = 0;
            #pragma unroll
            for (int k = 0; k < KNN; k++) if (bk[k] > mk) { mk = bk[k]; mp = k; }
            #pragma unroll
            for (int k = 0; k < KNN; k++) if (k == mp) bk[k] = nk;
            mk = 0;
            #pragma unroll
            for (int k = 0; k < KNN; k++) if (bk[k] > mk) mk = bk[k];
            unsigned hv = (unsigned)(mk >> 32);
            hv = (hv & 0x80000000u) ? (hv ^ 0x80000000u) : ~hv;
            thr = __uint_as_float(hv);
        }
    }

    unsigned long long res = 0;
    for (int r = 0; r < KNN; r++) {
        unsigned long long lm = 0xFFFFFFFFFFFFFFFFull;
        #pragma unroll
        for (int k = 0; k < KNN; k++) if (bk[k] < lm) lm = bk[k];
        unsigned long long wm = lm;
        #pragma unroll
        for (int o = 16; o; o >>= 1) {
            unsigned long long t = __shfl_xor_sync(0xffffffffu, wm, o);
            if (t < wm) wm = t;
        }
        if (lm == wm) {
            #pragma unroll
            for (int k = 0; k < KNN; k++) if (bk[k] == wm) bk[k] = 0xFFFFFFFFFFFFFFFFull;
        }
        if (lane == r) res = wm;
    }
    if (lane < KNN) g_nbr[qi*KNN + lane] = (int)(res & 0xFFFFFFFFu);
}

// =========================== gather + BN + ReLU + max ===========================
__global__ void __launch_bounds__(256)
gather_kernel(float* __restrict__ y) {
    const int tid = threadIdx.x;
    const int w = tid >> 5, lane = tid & 31;
    const int q = blockIdx.x*8 + w;              // global (b,m) id
    const int b = q >> 11;
    const int* nb = g_nbr + (size_t)q*KNN;
    const float4 sc = *(const float4*)&g_scale[lane*4];
    const float4 sh = *(const float4*)&g_shift[lane*4];
    const float* hb = g_h + (size_t)b*NN*COUT;

    float4 acc = make_float4(-3.4e38f,-3.4e38f,-3.4e38f,-3.4e38f);
    #pragma unroll
    for (int k = 0; k < KNN; k++) {
        int n = nb[k];
        float4 v = *(const float4*)&hb[(size_t)n*COUT + lane*4];
        float f;
        f = fmaxf(__fmaf_rn(v.x, sc.x, sh.x), 0.f); acc.x = fmaxf(acc.x, f);
        f = fmaxf(__fmaf_rn(v.y, sc.y, sh.y), 0.f); acc.y = fmaxf(acc.y, f);
        f = fmaxf(__fmaf_rn(v.z, sc.z, sh.z), 0.f); acc.z = fmaxf(acc.z, f);
        f = fmaxf(__fmaf_rn(v.w, sc.w, sh.w), 0.f); acc.w = fmaxf(acc.w, f);
    }
    *(float4*)&y[(size_t)q*COUT + lane*4] = acc;
}

// =============================== launch ===============================
// NOTE: launch order puts fps_kernel in the ncu-captured slot (index 3)
// so the next profile shows FPS instead of bnstat2. All kernels are on one
// stream, so this reordering is dependency-legal and perf-neutral:
// gemm -> bnstat1 -> bnstat2 (stat chain), then fps -> knn -> gather.
extern "C" void kernel_launch(void* const* d_in, const int* in_sizes, int n_in,
                              void* d_out, int out_size) {
    const float* x     = (const float*)d_in[0];
    const float* p1    = (const float*)d_in[1];
    const float* W     = (const float*)d_in[2];
    const float* gamma = (const float*)d_in[3];
    const float* beta  = (const float*)d_in[4];
    float* y  = (float*)d_out;
    float* p2 = y + Y_SIZE;

    const int KNN_SMEM  = 4*NN*4;          // 128 KB
    const int GEMM_SMEM = (128*65 + 64*128)*4;

    cudaFuncSetAttribute(knn_kernel,  cudaFuncAttributeMaxDynamicSharedMemorySize, KNN_SMEM);
    cudaFuncSetAttribute(gemm_kernel, cudaFuncAttributeMaxDynamicSharedMemorySize, GEMM_SMEM);

    gemm_kernel<<<ROWS/128, 256, GEMM_SMEM>>>(x, W);
    bnstat1<<<256, 128>>>();
    bnstat2<<<COUT, 256>>>(gamma, beta);
    fps_kernel<<<BB, 512>>>(p1, p2);
    knn_kernel<<<BB*(MM/8), 256, KNN_SMEM>>>(p1, p2);
    gather_kernel<<<(BB*MM)/8, 256>>>(y);
}